// round 2
// baseline (speedup 1.0000x reference)
#include <cuda_runtime.h>
#include <cuda_bf16.h>

// AngularDescriptor: q[i,d,l] = sum_{j<k in nbrs(i)} g_ij[d] * g_ik[d] * P_l(cos theta_jik)
// Strategy: per-atom warp. Phase 1: per-neighbor (20) Chebyshev basis + c_table
// contraction -> g[8], plus (dx,dy,dz,r) cached in shared (stride 13, coprime
// with 32 -> conflict-free). Phase 2: 190 pairs strided over 32 lanes, pure FMA.
// Phase 3: 5-stage shfl transpose-reduce so lane t holds q[atom, t] -> coalesced store.

#define WPB 8  // warps (atoms) per block

__global__ __launch_bounds__(WPB * 32) void ang_kernel(
    const int*   __restrict__ types,
    const float* __restrict__ pos,
    const int*   __restrict__ nbr,
    const float* __restrict__ ctab,
    float*       __restrict__ out,
    int natoms)
{
    __shared__ float sh[WPB][20 * 13];
    const int warp = threadIdx.x >> 5;
    const int lane = threadIdx.x & 31;
    const int atom = blockIdx.x * WPB + warp;
    if (atom >= natoms) return;
    float* S = sh[warp];

    const int   ti  = types[atom];
    const float pix = pos[atom * 3 + 0];
    const float piy = pos[atom * 3 + 1];
    const float piz = pos[atom * 3 + 2];

    // ---- Phase 1: per-neighbor g[8] and geometry (lanes 0..19) ----
    if (lane < 20) {
        const int n = nbr[atom * 20 + lane];
        const float dx = pos[n * 3 + 0] - pix;
        const float dy = pos[n * 3 + 1] - piy;
        const float dz = pos[n * 3 + 2] - piz;
        const float r  = sqrtf(dx * dx + dy * dy + dz * dz);

        // fc = 0.5*cos(pi*r/rc)+0.5 for r<rc else 0   (rc = 5)
        const float fc = (r < 5.0f) ? fmaf(0.5f, __cosf(r * 0.6283185307179586f), 0.5f)
                                    : 0.0f;
        const float xr = fmaf(r, 0.2f, -1.0f);       // r/rc - 1
        const float x  = fmaf(2.0f * xr, xr, -1.0f); // 2*(r/rc-1)^2 - 1
        const float h  = 0.5f * fc;

        float f[8];
        {
            float tp = 1.0f, tc = x;
            f[0] = (tp + 1.0f) * h;
            f[1] = (tc + 1.0f) * h;
            #pragma unroll
            for (int k = 2; k < 8; k++) {
                const float tn = fmaf(2.0f * x, tc, -tp);
                f[k] = (tn + 1.0f) * h;
                tp = tc; tc = tn;
            }
        }

        const int tj = types[n];
        const float4* c4 = reinterpret_cast<const float4*>(ctab + (ti * 4 + tj) * 64);

        const int base = lane * 13;
        S[base + 0] = dx;
        S[base + 1] = dy;
        S[base + 2] = dz;
        S[base + 3] = r;
        #pragma unroll
        for (int d = 0; d < 8; d++) {
            const float4 a = c4[d * 2 + 0];
            const float4 b = c4[d * 2 + 1];
            const float g = a.x * f[0] + a.y * f[1] + a.z * f[2] + a.w * f[3]
                          + b.x * f[4] + b.y * f[5] + b.z * f[6] + b.w * f[7];
            S[base + 4 + d] = g;
        }
    }
    __syncwarp();

    // ---- Phase 2: 190 pairs strided over 32 lanes ----
    float acc[32];
    #pragma unroll
    for (int i = 0; i < 32; i++) acc[i] = 0.0f;

    for (int p = lane; p < 190; p += 32) {
        // decode upper-triangular pair index p -> (j,k), M=20
        // base(j) = 19j - j(j-1)/2
        const float tf = sqrtf(fmaf(-8.0f, (float)p, 1521.0f));
        int j = (int)((39.0f - tf) * 0.5f);
        int base = 19 * j - ((j * (j - 1)) >> 1);
        if (p < base) { j--; base = 19 * j - ((j * (j - 1)) >> 1); }
        else { const int nx = base + (19 - j); if (p >= nx) { base = nx; j++; } }
        const int k = j + 1 + (p - base);

        const float* Sj = S + j * 13;
        const float* Sk = S + k * 13;

        const float dot = Sj[0] * Sk[0] + Sj[1] * Sk[1] + Sj[2] * Sk[2];
        const float den = fmaf(Sj[3], Sk[3], 1e-8f);
        const float c   = __fdividef(dot, den);
        const float c2  = c * c;
        const float P2  = fmaf(1.5f, c2, -0.5f);             // (3c^2-1)/2
        const float P3  = c * fmaf(2.5f, c2, -1.5f);         // (5c^3-3c)/2

        #pragma unroll
        for (int d = 0; d < 8; d++) {
            const float s = Sj[4 + d] * Sk[4 + d];
            acc[d * 4 + 0] += s;
            acc[d * 4 + 1] = fmaf(s, c,  acc[d * 4 + 1]);
            acc[d * 4 + 2] = fmaf(s, P2, acc[d * 4 + 2]);
            acc[d * 4 + 3] = fmaf(s, P3, acc[d * 4 + 3]);
        }
    }

    // ---- Phase 3: shfl transpose-reduce; lane t ends with sum over lanes of acc[t] ----
    #pragma unroll
    for (int m = 0; m < 16; m++) {
        const bool hi = (lane & 16) != 0;
        const float keep = hi ? acc[m + 16] : acc[m];
        const float send = hi ? acc[m]      : acc[m + 16];
        acc[m] = keep + __shfl_xor_sync(0xffffffffu, send, 16);
    }
    #pragma unroll
    for (int m = 0; m < 8; m++) {
        const bool hi = (lane & 8) != 0;
        const float keep = hi ? acc[m + 8] : acc[m];
        const float send = hi ? acc[m]     : acc[m + 8];
        acc[m] = keep + __shfl_xor_sync(0xffffffffu, send, 8);
    }
    #pragma unroll
    for (int m = 0; m < 4; m++) {
        const bool hi = (lane & 4) != 0;
        const float keep = hi ? acc[m + 4] : acc[m];
        const float send = hi ? acc[m]     : acc[m + 4];
        acc[m] = keep + __shfl_xor_sync(0xffffffffu, send, 4);
    }
    #pragma unroll
    for (int m = 0; m < 2; m++) {
        const bool hi = (lane & 2) != 0;
        const float keep = hi ? acc[m + 2] : acc[m];
        const float send = hi ? acc[m]     : acc[m + 2];
        acc[m] = keep + __shfl_xor_sync(0xffffffffu, send, 2);
    }
    {
        const bool hi = (lane & 1) != 0;
        const float keep = hi ? acc[1] : acc[0];
        const float send = hi ? acc[0] : acc[1];
        acc[0] = keep + __shfl_xor_sync(0xffffffffu, send, 1);
    }

    out[atom * 32 + lane] = acc[0];
}

extern "C" void kernel_launch(void* const* d_in, const int* in_sizes, int n_in,
                              void* d_out, int out_size) {
    const int*   types = (const int*)  d_in[0];
    const float* pos   = (const float*)d_in[1];
    const int*   nbrs  = (const int*)  d_in[2];
    const float* ctab  = (const float*)d_in[3];
    float*       out   = (float*)      d_out;

    const int natoms = in_sizes[0];
    const int blocks = (natoms + WPB - 1) / WPB;
    ang_kernel<<<blocks, WPB * 32>>>(types, pos, nbrs, ctab, out, natoms);
}

// round 7
// speedup vs baseline: 1.1083x; 1.1083x over previous
#include <cuda_runtime.h>
#include <cuda_bf16.h>

// AngularDescriptor via moment expansion:
//   q[i,d,l] = sum_{j<k} g_ij[d] g_ik[d] P_l(u_j . u_k)
//            = 0.5 * ( sum_p a_{lp} T_p[d]  -  sum_j g_ij[d]^2 )
//   T_p[d]   = sum_{|alpha|=p} w_alpha (sum_j g_ij[d] * u_j^alpha)^2
// One warp per atom. Phase 1: lanes 0..19 build per-neighbor g[8] and 20
// monomials of the unit vector, stored in shared (row stride 29, conflict-free).
// Phase 2: lane = d*4+grp accumulates 5 moments over a uniform 20-iteration
// neighbor loop (6 LDS + 6 FMA per iter). Epilogue: weighted squares, 8-shfl
// butterfly over the 4-lane d-group, per-l Legendre combine, coalesced store.

#define WPB 8  // warps (atoms) per block

// per-moment one-hot weight into bucket p (x=T0, y=T1, z=T2, w=T3)
__device__ const float4 WSEL[20] = {
    {1.f,0.f,0.f,0.f},                                          // 1
    {0.f,1.f,0.f,0.f},{0.f,1.f,0.f,0.f},{0.f,1.f,0.f,0.f},     // x y z
    {0.f,0.f,1.f,0.f},{0.f,0.f,1.f,0.f},{0.f,0.f,1.f,0.f},     // x2 y2 z2
    {0.f,0.f,2.f,0.f},{0.f,0.f,2.f,0.f},{0.f,0.f,2.f,0.f},     // xy xz yz
    {0.f,0.f,0.f,1.f},{0.f,0.f,0.f,1.f},{0.f,0.f,0.f,1.f},     // x3 y3 z3
    {0.f,0.f,0.f,3.f},{0.f,0.f,0.f,3.f},{0.f,0.f,0.f,3.f},     // x2y x2z y2x
    {0.f,0.f,0.f,3.f},{0.f,0.f,0.f,3.f},{0.f,0.f,0.f,3.f},     // y2z z2x z2y
    {0.f,0.f,0.f,6.f}                                           // xyz
};
// Legendre combine coefficients per l: q_pairfull = a.T
__device__ const float4 ACOEF[4] = {
    { 1.0f,  0.0f, 0.0f, 0.0f},   // P0
    { 0.0f,  1.0f, 0.0f, 0.0f},   // P1
    {-0.5f,  0.0f, 1.5f, 0.0f},   // P2 = 1.5 t^2 - 0.5
    { 0.0f, -1.5f, 0.0f, 2.5f}    // P3 = 2.5 t^3 - 1.5 t
};

__global__ __launch_bounds__(WPB * 32) void ang_kernel(
    const int*   __restrict__ types,
    const float* __restrict__ pos,
    const int*   __restrict__ nbr,
    const float* __restrict__ ctab,
    float*       __restrict__ out,
    int natoms)
{
    __shared__ float sh[WPB][20 * 29];
    const int warp = threadIdx.x >> 5;
    const int lane = threadIdx.x & 31;
    const int atom = blockIdx.x * WPB + warp;
    if (atom >= natoms) return;
    float* S = sh[warp];

    // ---- Phase 1: per-neighbor g[8] + monomials (lanes 0..19) ----
    if (lane < 20) {
        const int   ti  = types[atom];
        const float pix = pos[atom * 3 + 0];
        const float piy = pos[atom * 3 + 1];
        const float piz = pos[atom * 3 + 2];

        const int n = nbr[atom * 20 + lane];
        const float dx = pos[n * 3 + 0] - pix;
        const float dy = pos[n * 3 + 1] - piy;
        const float dz = pos[n * 3 + 2] - piz;
        const float r2 = dx * dx + dy * dy + dz * dz;
        const float rinv = rsqrtf(r2);
        const float r  = r2 * rinv;

        // Chebyshev radial basis * 0.5*fc  (rc = 5)
        const float fc = (r < 5.0f) ? fmaf(0.5f, __cosf(r * 0.6283185307179586f), 0.5f)
                                    : 0.0f;
        const float xr = fmaf(r, 0.2f, -1.0f);
        const float xx = fmaf(2.0f * xr, xr, -1.0f);
        const float h  = 0.5f * fc;

        float f[8];
        {
            float tp = 1.0f, tc = xx;
            f[0] = (tp + 1.0f) * h;
            f[1] = (tc + 1.0f) * h;
            #pragma unroll
            for (int k = 2; k < 8; k++) {
                const float tn = fmaf(2.0f * xx, tc, -tp);
                f[k] = (tn + 1.0f) * h;
                tp = tc; tc = tn;
            }
        }

        const int tj = types[n];
        const float4* c4 = reinterpret_cast<const float4*>(ctab + (ti * 4 + tj) * 64);
        float* R = S + lane * 29;
        #pragma unroll
        for (int d = 0; d < 8; d++) {
            const float4 a = c4[d * 2 + 0];
            const float4 b = c4[d * 2 + 1];
            R[d] = a.x * f[0] + a.y * f[1] + a.z * f[2] + a.w * f[3]
                 + b.x * f[4] + b.y * f[5] + b.z * f[6] + b.w * f[7];
        }

        // unit-vector monomials up to degree 3
        const float x = dx * rinv, y = dy * rinv, z = dz * rinv;
        const float x2 = x * x, y2 = y * y, z2 = z * z;
        const float xy = x * y, xz = x * z, yz = y * z;
        float* Mo = R + 8;
        Mo[0]  = 1.0f;
        Mo[1]  = x;       Mo[2]  = y;       Mo[3]  = z;
        Mo[4]  = x2;      Mo[5]  = y2;      Mo[6]  = z2;
        Mo[7]  = xy;      Mo[8]  = xz;      Mo[9]  = yz;
        Mo[10] = x2 * x;  Mo[11] = y2 * y;  Mo[12] = z2 * z;
        Mo[13] = x2 * y;  Mo[14] = x2 * z;  Mo[15] = y2 * x;
        Mo[16] = y2 * z;  Mo[17] = z2 * x;  Mo[18] = z2 * y;
        Mo[19] = xy * z;
    }
    __syncwarp();

    // ---- Phase 2: moment accumulation; lane = d*4 + grp handles 5 moments ----
    const int d   = lane >> 2;
    const int grp = lane & 3;
    const int moff = 8 + grp * 5;

    float M0 = 0.f, M1 = 0.f, M2 = 0.f, M3 = 0.f, M4 = 0.f, D = 0.f;
    #pragma unroll
    for (int j = 0; j < 20; j++) {
        const float* R = S + j * 29;
        const float g = R[d];
        D  = fmaf(g, g, D);
        M0 = fmaf(g, R[moff + 0], M0);
        M1 = fmaf(g, R[moff + 1], M1);
        M2 = fmaf(g, R[moff + 2], M2);
        M3 = fmaf(g, R[moff + 3], M3);
        M4 = fmaf(g, R[moff + 4], M4);
    }

    // ---- Epilogue: weighted squares into T buckets ----
    float T0 = 0.f, T1 = 0.f, T2 = 0.f, T3 = 0.f;
    {
        const float4* W = WSEL + grp * 5;
        float s;
        float4 w;
        s = M0 * M0; w = W[0];
        T0 = fmaf(s, w.x, T0); T1 = fmaf(s, w.y, T1); T2 = fmaf(s, w.z, T2); T3 = fmaf(s, w.w, T3);
        s = M1 * M1; w = W[1];
        T0 = fmaf(s, w.x, T0); T1 = fmaf(s, w.y, T1); T2 = fmaf(s, w.z, T2); T3 = fmaf(s, w.w, T3);
        s = M2 * M2; w = W[2];
        T0 = fmaf(s, w.x, T0); T1 = fmaf(s, w.y, T1); T2 = fmaf(s, w.z, T2); T3 = fmaf(s, w.w, T3);
        s = M3 * M3; w = W[3];
        T0 = fmaf(s, w.x, T0); T1 = fmaf(s, w.y, T1); T2 = fmaf(s, w.z, T2); T3 = fmaf(s, w.w, T3);
        s = M4 * M4; w = W[4];
        T0 = fmaf(s, w.x, T0); T1 = fmaf(s, w.y, T1); T2 = fmaf(s, w.z, T2); T3 = fmaf(s, w.w, T3);
    }

    // butterfly over the 4-lane d-group: every lane gets full T0..T3
    T0 += __shfl_xor_sync(0xffffffffu, T0, 1);
    T0 += __shfl_xor_sync(0xffffffffu, T0, 2);
    T1 += __shfl_xor_sync(0xffffffffu, T1, 1);
    T1 += __shfl_xor_sync(0xffffffffu, T1, 2);
    T2 += __shfl_xor_sync(0xffffffffu, T2, 1);
    T2 += __shfl_xor_sync(0xffffffffu, T2, 2);
    T3 += __shfl_xor_sync(0xffffffffu, T3, 1);
    T3 += __shfl_xor_sync(0xffffffffu, T3, 2);

    // per-l Legendre combine; lane index already equals d*4 + l
    const float4 a = ACOEF[grp];
    float q = a.x * T0;
    q = fmaf(a.y, T1, q);
    q = fmaf(a.z, T2, q);
    q = fmaf(a.w, T3, q);
    out[atom * 32 + lane] = 0.5f * (q - D);
}

extern "C" void kernel_launch(void* const* d_in, const int* in_sizes, int n_in,
                              void* d_out, int out_size) {
    const int*   types = (const int*)  d_in[0];
    const float* pos   = (const float*)d_in[1];
    const int*   nbrs  = (const int*)  d_in[2];
    const float* ctab  = (const float*)d_in[3];
    float*       out   = (float*)      d_out;

    const int natoms = in_sizes[0];
    const int blocks = (natoms + WPB - 1) / WPB;
    ang_kernel<<<blocks, WPB * 32>>>(types, pos, nbrs, ctab, out, natoms);
}